// round 10
// baseline (speedup 1.0000x reference)
#include <cuda_runtime.h>

#define BATCH 4096

// ---------------- Device scratch ----------------
__device__ unsigned g_w1p[20];                         // 25 sign bits per filter
__device__ __align__(16) unsigned g_w2q[50*16];        // per filter: 500-bit window layout (p = t*20+c)
__device__ __align__(16) unsigned g_w3p[1024*80];      // per out-neuron: 2450 bits, order j' = pix*50+c, pad 80
__device__ unsigned g_w4p[10*32];                      // per out-neuron: 1024 sign bits
__device__ unsigned g_packed1[BATCH*324];              // conv2 input: padded 18x18, 20 ch bits per pixel
__device__ __align__(16) unsigned g_packed2[BATCH*80]; // fc3 input bits (order pix*50+c), padded

// ---------------- w3 packing: block per out-neuron, coalesced + smem transpose ----------------
__global__ void __launch_bounds__(128) pack_w3_kernel(const float* __restrict__ w3) {
    __shared__ unsigned char sb[2450];
    int o = blockIdx.x, tid = threadIdx.x;
    const float* row = w3 + o * 2450;
    for (int j = tid; j < 2450; j += 128) sb[j] = (row[j] > 0.0f);
    __syncthreads();
    if (tid < 80) {
        unsigned m = 0; int base = tid * 32;
        for (int k = 0; k < 32; k++) {
            int jp = base + k;
            if (jp < 2450) {
                int pix = jp / 50, c = jp % 50;   // orig flat index = c*49 + pix
                m |= (unsigned)sb[c*49 + pix] << k;
            }
        }
        g_w3p[o*80 + tid] = m;
    }
}

// ---------------- small weights: w1 | w2q | w4 ----------------
// ranges: [0,20) w1 | [20,820) w2q | [820,1140) w4
__global__ void pack_wsm_kernel(const float* __restrict__ w1, const float* __restrict__ w2,
                                const float* __restrict__ w4) {
    int id = blockIdx.x * blockDim.x + threadIdx.x;
    if (id < 20) {
        unsigned m = 0;
        #pragma unroll
        for (int t = 0; t < 25; t++) m |= (unsigned)(w1[id*25 + t] > 0.0f) << t;
        g_w1p[id] = m;
    } else if (id < 820) {
        int idx = id - 20; int f = idx / 16, w = idx % 16;
        unsigned m = 0;
        for (int k = 0; k < 32; k++) {
            int p = w*32 + k;
            if (p < 500) {
                int t = p / 20, c = p % 20;
                m |= (unsigned)(w2[f*500 + c*25 + t] > 0.0f) << k;
            }
        }
        g_w2q[idx] = m;
    } else if (id < 1140) {
        int idx = id - 820; int o = idx / 32, w = idx % 32;
        unsigned m = 0;
        #pragma unroll
        for (int k = 0; k < 32; k++) m |= (unsigned)(w4[o*1024 + w*32 + k] > 0.0f) << k;
        g_w4p[idx] = m;
    }
}

// ---------------- fused x-pack + conv1 + relu + maxpool2 + sign; one image per CTA ----------------
__global__ void __launch_bounds__(224) conv1f_kernel(const float* __restrict__ x,
                                                     const float* __restrict__ b1) {
    __shared__ float sx[784];
    __shared__ unsigned smr[32], spr[32];
    __shared__ unsigned w1s[20];
    __shared__ float b1s[20];
    int tid = threadIdx.x, b = blockIdx.x;
    if (tid < 20) { w1s[tid] = g_w1p[tid]; b1s[tid] = b1[tid]; }
    for (int i = tid; i < 784; i += 224) sx[i] = x[b*784 + i];
    if (tid < 80) g_packed2[b*80 + tid] = 0;          // zero fc3-input row for conv2's atomicOr
    __syncthreads();

    if (tid < 32) {
        int r = tid; unsigned m = 0, p = 0;
        if (r >= 2 && r < 30) {
            const float* row = sx + (r - 2) * 28;
            #pragma unroll
            for (int xx = 0; xx < 28; xx++) {
                float v = row[xx];
                m |= (unsigned)(v != 0.0f) << (xx + 2);
                p |= (unsigned)(v > 0.0f)  << (xx + 2);
            }
        }
        smr[r] = m; spr[r] = p;
    }
    __syncthreads();

    unsigned* p1b = g_packed1 + b * 324;
    // zero the 128 border cells of the 18x18 padded image
    if (tid < 128) {
        int y, xx;
        if (tid < 72) { int ry = tid / 18; y = (ry < 2) ? ry : ry + 14; xx = tid % 18; }
        else { int j = tid - 72; int cx = j % 4; xx = (cx < 2) ? cx : cx + 14; y = 2 + j / 4; }
        p1b[y*18 + xx] = 0u;
    }

    if (tid < 196) {
        int py = tid / 14, px = tid % 14;
        unsigned mr[6], pr[6];
        #pragma unroll
        for (int i = 0; i < 6; i++) { mr[i] = smr[2*py + i]; pr[i] = spr[2*py + i]; }

        unsigned M[4], P[4]; int pm[4];
        #pragma unroll
        for (int dy = 0; dy < 2; dy++)
        #pragma unroll
        for (int dx = 0; dx < 2; dx++) {
            int sh = 2*px + dx;
            unsigned m = 0, p = 0;
            #pragma unroll
            for (int ky = 0; ky < 5; ky++) {
                m |= ((mr[dy + ky] >> sh) & 31u) << (5*ky);
                p |= ((pr[dy + ky] >> sh) & 31u) << (5*ky);
            }
            int w = dy*2 + dx;
            M[w] = m; P[w] = p; pm[w] = __popc(m);
        }

        unsigned word = 0;
        #pragma unroll
        for (int c = 0; c < 20; c++) {
            unsigned wp = w1s[c];
            int d0 = 2*__popc(M[0] & ~(P[0] ^ wp)) - pm[0];
            int d1 = 2*__popc(M[1] & ~(P[1] ^ wp)) - pm[1];
            int d2 = 2*__popc(M[2] & ~(P[2] ^ wp)) - pm[2];
            int d3 = 2*__popc(M[3] & ~(P[3] ^ wp)) - pm[3];
            int mx = max(max(d0, d1), max(d2, d3));
            if ((float)mx + b1s[c] > 0.0f) word |= 1u << c;
        }
        p1b[(py + 2)*18 + (px + 2)] = word;
    }
}

// ---------------- conv2: 4 sequential windows, single W[16], padded loads ----------------
__global__ void __launch_bounds__(128, 8) conv2_kernel(const float* __restrict__ b2) {
    __shared__ __align__(16) unsigned sw[50*16];
    __shared__ int thr[50];
    int tid = threadIdx.x;
    for (int t = tid; t < 800; t += 128) sw[t] = g_w2q[t];
    if (tid < 50) thr[tid] = (int)floorf(-b2[tid]) + 1;
    __syncthreads();

    int id = blockIdx.x * 128 + tid;                 // 1568*128 = 4096*49
    int b = id / 49, pix = id % 49;
    int py = pix / 7, px = pix % 7;
    const unsigned* inb = g_packed1 + b * 324;

    unsigned long long bits = 0ull;

    #pragma unroll 1
    for (int win = 0; win < 4; win++) {
        const unsigned* base = inb + (py*2 + (win >> 1))*18 + (px*2 + (win & 1));

        unsigned W[16];
        {
            unsigned long long acc = 0; int off = 0, wi = 0;
            #pragma unroll
            for (int ky = 0; ky < 5; ky++)
            #pragma unroll
            for (int kx = 0; kx < 5; kx++) {
                unsigned long long v = base[ky*18 + kx];
                acc |= v << off;
                off += 20;
                if (off >= 32) { W[wi++] = (unsigned)acc; acc >>= 32; off -= 32; }
            }
            W[wi] = (unsigned)acc;
        }

        int S = 0;
        #pragma unroll
        for (int j = 0; j < 16; j++) S += __popc(W[j]);

        #pragma unroll 2
        for (int f = 0; f < 50; f++) {
            const uint4* fp = (const uint4*)&sw[f*16];
            int P = 0;
            #pragma unroll
            for (int q = 0; q < 4; q++) {
                uint4 w = fp[q];
                P += __popc(W[q*4+0] & w.x) + __popc(W[q*4+1] & w.y)
                   + __popc(W[q*4+2] & w.z) + __popc(W[q*4+3] & w.w);
            }
            bits |= (unsigned long long)(2*P - S >= thr[f]) << f;
        }
    }

    unsigned* row = g_packed2 + b * 80;
    int base = pix * 50;
    int w0 = base >> 5, sh = base & 31;
    unsigned long long lo = bits << sh;
    atomicOr(&row[w0],     (unsigned)lo);
    atomicOr(&row[w0 + 1], (unsigned)(lo >> 32));
    if (sh >= 15) atomicOr(&row[w0 + 2], (unsigned)(bits >> (64 - sh)));
}

// ---------------- fused fc3 + fc4: one CTA per 8 batch rows ----------------
__global__ void __launch_bounds__(256) fc34_kernel(const float* __restrict__ b3,
                                                   const float* __restrict__ b4,
                                                   float* __restrict__ out) {
    __shared__ __align__(16) unsigned sa[8*80];
    __shared__ int sna[8];
    __shared__ unsigned sp[8*32];
    __shared__ unsigned w4s[320];
    __shared__ float b4s[10];
    int tid = threadIdx.x;
    int b0 = blockIdx.x * 8;

    if (tid < 160) ((uint4*)sa)[tid] = ((const uint4*)(g_packed2 + b0*80))[tid];
    if (tid >= 160 && tid < 170) b4s[tid - 160] = b4[tid - 160];
    for (int t = tid; t < 320; t += 256) w4s[t] = g_w4p[t];
    __syncthreads();
    if (tid < 8) {
        int s = 0;
        #pragma unroll 8
        for (int i = 0; i < 80; i++) s += __popc(sa[tid*80 + i]);
        sna[tid] = s;
    }
    __syncthreads();

    // fc3: outputs tid + 256*j, j = 0..3
    const uint4* wr0 = (const uint4*)(g_w3p + (tid      )*80);
    const uint4* wr1 = (const uint4*)(g_w3p + (tid + 256)*80);
    const uint4* wr2 = (const uint4*)(g_w3p + (tid + 512)*80);
    const uint4* wr3 = (const uint4*)(g_w3p + (tid + 768)*80);

    int cnt[4][8];
    #pragma unroll
    for (int j = 0; j < 4; j++)
        #pragma unroll
        for (int bb = 0; bb < 8; bb++) cnt[j][bb] = 0;

    #pragma unroll 2
    for (int i = 0; i < 20; i++) {
        uint4 w[4] = {wr0[i], wr1[i], wr2[i], wr3[i]};
        #pragma unroll
        for (int bb = 0; bb < 8; bb++) {
            uint4 a = *(const uint4*)&sa[bb*80 + i*4];
            #pragma unroll
            for (int j = 0; j < 4; j++) {
                cnt[j][bb] += __popc(a.x & w[j].x) + __popc(a.y & w[j].y)
                            + __popc(a.z & w[j].z) + __popc(a.w & w[j].w);
            }
        }
    }

    #pragma unroll
    for (int j = 0; j < 4; j++) {
        int o = tid + 256*j;
        float bias = b3[o];
        int widx = o >> 5;
        #pragma unroll
        for (int bb = 0; bb < 8; bb++) {
            float val = (float)(2*cnt[j][bb] - sna[bb]) + bias;
            unsigned word = __ballot_sync(0xffffffffu, val > 0.0f);
            if ((tid & 31) == 0) sp[bb*32 + widx] = word;
        }
    }
    __syncthreads();

    // fc4: 80 work items (bb, k)
    if (tid < 80) {
        int bb = tid / 10, k = tid % 10;
        int na = 0, c2 = 0;
        #pragma unroll
        for (int i = 0; i < 32; i++) {
            unsigned a = sp[bb*32 + i];
            na += __popc(a);
            c2 += __popc(a & w4s[k*32 + i]);
        }
        out[(b0 + bb)*10 + k] = (float)(2*c2 - na) + b4s[k];
    }
}

// ---------------- launch ----------------
extern "C" void kernel_launch(void* const* d_in, const int* in_sizes, int n_in,
                              void* d_out, int out_size) {
    const float* x  = (const float*)d_in[0];
    const float* w1 = (const float*)d_in[1];
    const float* b1 = (const float*)d_in[2];
    const float* w2 = (const float*)d_in[3];
    const float* b2 = (const float*)d_in[4];
    const float* w3 = (const float*)d_in[5];
    const float* b3 = (const float*)d_in[6];
    const float* w4 = (const float*)d_in[7];
    const float* b4 = (const float*)d_in[8];
    float* out = (float*)d_out;

    pack_w3_kernel<<<1024, 128>>>(w3);               // block per out-neuron
    pack_wsm_kernel<<<9, 128>>>(w1, w2, w4);         // 1140 items
    conv1f_kernel<<<4096, 224>>>(x, b1);             // one image per CTA
    conv2_kernel<<<1568, 128>>>(b2);                 // 4096*49
    fc34_kernel<<<512, 256>>>(b3, b4, out);          // 8 batch rows per CTA
}